// round 1
// baseline (speedup 1.0000x reference)
#include <cuda_runtime.h>
#include <math.h>

// Problem constants
#define Bb     32
#define Dd     64
#define Hh     64
#define Ww     64
#define Kk     512
#define HWs    4096          // H*W
#define DHW    262144        // D*H*W
#define Nn     131072        // B*H*W
#define EPSf   1e-5f

#define C_CTAS 128           // partial-sum CTAs

// Scratch (static __device__ arrays: allocation-free per harness rules)
__device__ float d_ec[Kk];                      // ||e_k||^2
__device__ int   d_counts[Kk];                  // assignment counts
__device__ int   d_idx[Nn];                     // argmin per vector
__device__ float d_scale[Kk];                   // 1/(bias*norm_c[k])
__device__ float d_partial[C_CTAS * Dd * Kk];   // 16 MB partial embed sums

// ---------------------------------------------------------------------------
// Kernel A: zero counts + precompute ||e_k||^2
// ---------------------------------------------------------------------------
__global__ void prep_kernel(const float* __restrict__ emb) {
    int k = threadIdx.x;          // 512 threads
    d_counts[k] = 0;
    const float4* r = (const float4*)(emb + (k << 6));
    float s = 0.f;
#pragma unroll
    for (int i = 0; i < 16; i++) {
        float4 v = __ldg(r + i);
        s += v.x * v.x + v.y * v.y + v.z * v.z + v.w * v.w;
    }
    d_ec[k] = s;
}

// ---------------------------------------------------------------------------
// Kernel B: nearest-code assignment + quantized output
//   CTA = 512 threads, 1 vector/thread. Full codebook in smem.
//   Score = ||e||^2 - 2*f.e via packed fp32x2 FMA (2x fp32 rate on sm_100).
// ---------------------------------------------------------------------------
__global__ __launch_bounds__(512, 1)
void assign_kernel(const float* __restrict__ x,
                   const float* __restrict__ emb,
                   float* __restrict__ q) {
    extern __shared__ float se[];          // [Kk*Dd] emb + [Kk] ec
    float* se_ec = se + Kk * Dd;

    // cooperative load of codebook (128 KB) + ec
    {
        const float4* g = (const float4*)emb;
        float4*       s4 = (float4*)se;
        for (int i = threadIdx.x; i < (Kk * Dd) / 4; i += 512)
            s4[i] = __ldg(g + i);
        se_ec[threadIdx.x] = d_ec[threadIdx.x];
    }
    __syncthreads();

    int n  = blockIdx.x * 512 + threadIdx.x;
    int b  = n >> 12;
    int hw = n & 4095;
    const float* xp = x + (size_t)b * DHW + hw;

    // load this thread's vector, packed into 32 x f32x2
    unsigned long long fp[32];
#pragma unroll
    for (int i = 0; i < 32; i++) {
        float a = __ldg(xp + ((2 * i)     << 12));
        float c = __ldg(xp + ((2 * i + 1) << 12));
        unsigned long long p;
        asm("mov.b64 %0, {%1, %2};" : "=l"(p) : "f"(a), "f"(c));
        fp[i] = p;
    }

    float best = 3.4e38f;
    int   bi   = 0;
    for (int k = 0; k < Kk; k++) {
        const ulonglong2* er = (const ulonglong2*)(se + (k << 6));
        unsigned long long a0 = 0ull, a1 = 0ull;   // two accumulators (break RAW chain)
#pragma unroll
        for (int i = 0; i < 16; i++) {
            ulonglong2 ev = er[i];                 // LDS.128, warp-broadcast
            asm("fma.rn.f32x2 %0, %1, %2, %0;" : "+l"(a0) : "l"(fp[2 * i]),     "l"(ev.x));
            asm("fma.rn.f32x2 %0, %1, %2, %0;" : "+l"(a1) : "l"(fp[2 * i + 1]), "l"(ev.y));
        }
        float l0, h0, l1, h1;
        asm("mov.b64 {%0, %1}, %2;" : "=f"(l0), "=f"(h0) : "l"(a0));
        asm("mov.b64 {%0, %1}, %2;" : "=f"(l1), "=f"(h1) : "l"(a1));
        float dot = (l0 + l1) + (h0 + h1);
        float sc  = fmaf(dot, -2.f, se_ec[k]);
        if (sc < best) { best = sc; bi = k; }      // strict < keeps first index (argmin semantics)
    }

    d_idx[n] = bi;
    atomicAdd(&d_counts[bi], 1);

    // write quantized vector: read winning row from global (L2-resident), scatter-store
    const float4* er4 = (const float4*)(emb + (bi << 6));
    float* op = q + (size_t)b * DHW + hw;
#pragma unroll
    for (int i = 0; i < 16; i++) {
        float4 v = __ldg(er4 + i);
        op[((4 * i)     << 12)] = v.x;
        op[((4 * i + 1) << 12)] = v.y;
        op[((4 * i + 2) << 12)] = v.z;
        op[((4 * i + 3) << 12)] = v.w;
    }
}

// ---------------------------------------------------------------------------
// Kernel C: per-CTA partial embed sums via smem-privatized atomics
//   128 CTAs x 256 threads, 1024 vectors per CTA. smem histogram [D][K] 128KB.
// ---------------------------------------------------------------------------
__global__ __launch_bounds__(256, 1)
void sums_kernel(const float* __restrict__ x) {
    extern __shared__ float s[];               // Dd*Kk floats
    for (int i = threadIdx.x; i < Dd * Kk; i += 256) s[i] = 0.f;
    __syncthreads();

    int base = blockIdx.x * 1024;
#pragma unroll
    for (int v = 0; v < 4; v++) {
        int n  = base + v * 256 + threadIdx.x;
        int ix = d_idx[n];
        int b  = n >> 12;
        int hw = n & 4095;
        const float* xp = x + (size_t)b * DHW + hw;
#pragma unroll
        for (int d = 0; d < Dd; d++)
            atomicAdd(&s[(d << 9) + ix], __ldg(xp + (d << 12)));
    }
    __syncthreads();

    float* pp = d_partial + (size_t)blockIdx.x * (Dd * Kk);
    for (int i = threadIdx.x; i < Dd * Kk; i += 256) pp[i] = s[i];
}

// ---------------------------------------------------------------------------
// Kernel D1: counts EMA -> norm factor per code  (single CTA, deterministic)
// ---------------------------------------------------------------------------
__device__ __forceinline__ int decode_scalar_int(const int* p) {
    int v = *p;
    if (v >= 0 && v < 1000000) return v;          // passed as int32
    return (int)__int_as_float(v);                // passed as float32 bits
}

__global__ void norm_kernel(const float* __restrict__ ema_c,
                            const int* __restrict__ counter) {
    __shared__ float sh[Kk];
    __shared__ float tot;
    int k = threadIdx.x;

    int   cnt  = decode_scalar_int(counter) + 1;
    float bias = 1.f - (float)pow(0.99, (double)cnt);

    float avg_c = (ema_c[k] * 0.99f + (float)d_counts[k] * (1.0f - 0.99f)) / bias;
    sh[k] = avg_c;
    __syncthreads();
    if (k == 0) {
        float sum = 0.f;
        for (int i = 0; i < Kk; i++) sum += sh[i];
        tot = sum;
    }
    __syncthreads();
    float nn   = tot;
    float norm = (avg_c + EPSf) / (nn + Kk * EPSf) * nn;
    d_scale[k] = 1.f / (bias * norm);
}

// ---------------------------------------------------------------------------
// Kernel D2: reduce partials + emit new_weight [K, D]
// ---------------------------------------------------------------------------
__global__ __launch_bounds__(256)
void weight_kernel(const float* __restrict__ ema_e,
                   const float* __restrict__ emb,
                   const int* __restrict__ training,
                   float* __restrict__ w) {
    int j = blockIdx.x * 256 + threadIdx.x;    // 0..32767 over [D, K]
    int d = j >> 9;
    int k = j & 511;

    int tr = decode_scalar_int(training);
    if (tr != 0) {
        float S = 0.f;
#pragma unroll 4
        for (int c = 0; c < C_CTAS; c++)
            S += d_partial[(size_t)c * (Dd * Kk) + j];
        float nhe = ema_e[j] * 0.99f + S * (1.0f - 0.99f);
        w[(k << 6) + d] = nhe * d_scale[k];
    } else {
        w[(k << 6) + d] = emb[(k << 6) + d];
    }
}

// ---------------------------------------------------------------------------
extern "C" void kernel_launch(void* const* d_in, const int* in_sizes, int n_in,
                              void* d_out, int out_size) {
    const float* x        = (const float*)d_in[0];
    const float* emb      = (const float*)d_in[1];
    const float* ema_c    = (const float*)d_in[2];
    const float* ema_e    = (const float*)d_in[3];
    const int*   counter  = (const int*)d_in[4];
    const int*   training = (const int*)d_in[5];

    float* out = (float*)d_out;
    float* q   = out;                          // [B, D, H, W]
    float* w   = out + (size_t)Bb * DHW;       // [K, D]

    const int SMEM_B = (Kk * Dd + Kk) * sizeof(float);   // 133120
    const int SMEM_C = (Kk * Dd) * sizeof(float);        // 131072
    cudaFuncSetAttribute(assign_kernel, cudaFuncAttributeMaxDynamicSharedMemorySize, SMEM_B);
    cudaFuncSetAttribute(sums_kernel,   cudaFuncAttributeMaxDynamicSharedMemorySize, SMEM_C);

    prep_kernel  <<<1,   512>>>(emb);
    assign_kernel<<<256, 512, SMEM_B>>>(x, emb, q);
    sums_kernel  <<<C_CTAS, 256, SMEM_C>>>(x);
    norm_kernel  <<<1,   Kk>>>(ema_c, counter);
    weight_kernel<<<Dd * Kk / 256, 256>>>(ema_e, emb, training, w);
}

// round 2
// speedup vs baseline: 1.4787x; 1.4787x over previous
#include <cuda_runtime.h>
#include <math.h>

// Problem constants
#define Bb     32
#define Dd     64
#define Kk     512
#define DHW    262144        // D*H*W
#define Nn     131072        // B*H*W
#define EPSf   1e-5f

// Scratch (static __device__ arrays: allocation-free per harness rules)
__device__ float d_ec[Kk];          // ||e_k||^2
__device__ int   d_counts[Kk];      // assignment counts
__device__ float d_sums[Dd * Kk];   // embed sums [D][K]
__device__ float d_scale[Kk];       // 1/(bias*norm_c[k])

// ---------------------------------------------------------------------------
// Kernel A: zero sums/counts + precompute ||e_k||^2.   grid 64 x 512
// ---------------------------------------------------------------------------
__global__ void prep_kernel(const float* __restrict__ emb) {
    int t = threadIdx.x;
    int i = blockIdx.x * 512 + t;
    if (i < Dd * Kk) d_sums[i] = 0.f;
    if (blockIdx.x == 0) {
        d_counts[t] = 0;
        const float4* r = (const float4*)(emb + (t << 6));
        float s = 0.f;
#pragma unroll
        for (int j = 0; j < 16; j++) {
            float4 v = __ldg(r + j);
            s += v.x * v.x + v.y * v.y + v.z * v.z + v.w * v.w;
        }
        d_ec[t] = s;
    }
}

// ---------------------------------------------------------------------------
// Kernel B: nearest-code assignment + quantized output + fused EMA sums.
//   256 threads/CTA, 2 vectors/thread (512 vectors/CTA), 256 CTAs.
//   Full codebook in smem; packed fp32x2 FMA; 4 independent accum chains.
// ---------------------------------------------------------------------------
__global__ __launch_bounds__(256, 1)
void assign_kernel(const float* __restrict__ x,
                   const float* __restrict__ emb,
                   float* __restrict__ q) {
    extern __shared__ float se[];          // [Kk*Dd] emb + [Kk] ec
    float* se_ec = se + Kk * Dd;

    // cooperative load of codebook (128 KB) + ec
    {
        const float4* g = (const float4*)emb;
        float4*       s4 = (float4*)se;
        for (int i = threadIdx.x; i < (Kk * Dd) / 4; i += 256)
            s4[i] = __ldg(g + i);
        se_ec[threadIdx.x] = d_ec[threadIdx.x];
        se_ec[threadIdx.x + 256] = d_ec[threadIdx.x + 256];
    }
    __syncthreads();

    int n0 = blockIdx.x * 512 + threadIdx.x;    // vector A
    int n1 = n0 + 256;                          // vector B (same batch image)
    int b   = n0 >> 12;
    int hw0 = n0 & 4095;
    int hw1 = n1 & 4095;
    const float* xp0 = x + (size_t)b * DHW + hw0;
    const float* xp1 = x + (size_t)b * DHW + hw1;

    // load both vectors, packed into 32 x f32x2 each
    unsigned long long fa[32], fb[32];
#pragma unroll
    for (int i = 0; i < 32; i++) {
        float a0 = __ldg(xp0 + ((2 * i)     << 12));
        float a1 = __ldg(xp0 + ((2 * i + 1) << 12));
        float c0 = __ldg(xp1 + ((2 * i)     << 12));
        float c1 = __ldg(xp1 + ((2 * i + 1) << 12));
        asm("mov.b64 %0, {%1, %2};" : "=l"(fa[i]) : "f"(a0), "f"(a1));
        asm("mov.b64 %0, {%1, %2};" : "=l"(fb[i]) : "f"(c0), "f"(c1));
    }

    float bestA = 3.4e38f, bestB = 3.4e38f;
    int   biA = 0, biB = 0;
    for (int k = 0; k < Kk; k++) {
        const ulonglong2* er = (const ulonglong2*)(se + (k << 6));
        unsigned long long a0 = 0ull, a1 = 0ull, b0 = 0ull, b1 = 0ull;
#pragma unroll
        for (int i = 0; i < 16; i++) {
            ulonglong2 ev = er[i];                 // LDS.128, warp-broadcast
            asm("fma.rn.f32x2 %0, %1, %2, %0;" : "+l"(a0) : "l"(fa[2 * i]),     "l"(ev.x));
            asm("fma.rn.f32x2 %0, %1, %2, %0;" : "+l"(a1) : "l"(fa[2 * i + 1]), "l"(ev.y));
            asm("fma.rn.f32x2 %0, %1, %2, %0;" : "+l"(b0) : "l"(fb[2 * i]),     "l"(ev.x));
            asm("fma.rn.f32x2 %0, %1, %2, %0;" : "+l"(b1) : "l"(fb[2 * i + 1]), "l"(ev.y));
        }
        float ec = se_ec[k];
        float l0, h0, l1, h1;
        asm("mov.b64 {%0, %1}, %2;" : "=f"(l0), "=f"(h0) : "l"(a0));
        asm("mov.b64 {%0, %1}, %2;" : "=f"(l1), "=f"(h1) : "l"(a1));
        float scA = fmaf((l0 + l1) + (h0 + h1), -2.f, ec);
        asm("mov.b64 {%0, %1}, %2;" : "=f"(l0), "=f"(h0) : "l"(b0));
        asm("mov.b64 {%0, %1}, %2;" : "=f"(l1), "=f"(h1) : "l"(b1));
        float scB = fmaf((l0 + l1) + (h0 + h1), -2.f, ec);
        if (scA < bestA) { bestA = scA; biA = k; }
        if (scB < bestB) { bestB = scB; biB = k; }
    }

    atomicAdd(&d_counts[biA], 1);
    atomicAdd(&d_counts[biB], 1);

    // fused EMA embed sums: scatter this thread's vectors into d_sums[d][k]
    // (result unused -> ptxas emits RED.E.ADD.F32, fire-and-forget to L2)
#pragma unroll
    for (int i = 0; i < 32; i++) {
        float a0, a1, c0, c1;
        asm("mov.b64 {%0, %1}, %2;" : "=f"(a0), "=f"(a1) : "l"(fa[i]));
        asm("mov.b64 {%0, %1}, %2;" : "=f"(c0), "=f"(c1) : "l"(fb[i]));
        atomicAdd(&d_sums[((2 * i)     << 9) + biA], a0);
        atomicAdd(&d_sums[((2 * i + 1) << 9) + biA], a1);
        atomicAdd(&d_sums[((2 * i)     << 9) + biB], c0);
        atomicAdd(&d_sums[((2 * i + 1) << 9) + biB], c1);
    }

    // write quantized vectors from smem codebook, scatter-store
    const float4* eA = (const float4*)(se + (biA << 6));
    const float4* eB = (const float4*)(se + (biB << 6));
    float* op0 = q + (size_t)b * DHW + hw0;
    float* op1 = q + (size_t)b * DHW + hw1;
#pragma unroll
    for (int i = 0; i < 16; i++) {
        float4 v = eA[i];
        op0[((4 * i)     << 12)] = v.x;
        op0[((4 * i + 1) << 12)] = v.y;
        op0[((4 * i + 2) << 12)] = v.z;
        op0[((4 * i + 3) << 12)] = v.w;
        float4 w = eB[i];
        op1[((4 * i)     << 12)] = w.x;
        op1[((4 * i + 1) << 12)] = w.y;
        op1[((4 * i + 2) << 12)] = w.z;
        op1[((4 * i + 3) << 12)] = w.w;
    }
}

// ---------------------------------------------------------------------------
// Kernel C: counts EMA -> norm factor per code (single CTA, parallel reduce)
// ---------------------------------------------------------------------------
__device__ __forceinline__ int decode_scalar_int(const int* p) {
    int v = *p;
    if (v >= 0 && v < 1000000) return v;          // passed as int32
    return (int)__int_as_float(v);                // passed as float32 bits
}

__global__ void norm_kernel(const float* __restrict__ ema_c,
                            const int* __restrict__ counter) {
    __shared__ float wsum[16];
    __shared__ float tot;
    int k = threadIdx.x;          // 512 threads

    int   cnt  = decode_scalar_int(counter) + 1;
    float bias = 1.f - (float)pow(0.99, (double)cnt);

    float avg_c = (ema_c[k] * 0.99f + (float)d_counts[k] * 0.01f) / bias;

    float s = avg_c;
#pragma unroll
    for (int o = 16; o > 0; o >>= 1) s += __shfl_xor_sync(0xffffffffu, s, o);
    if ((k & 31) == 0) wsum[k >> 5] = s;
    __syncthreads();
    if (k < 32) {
        float t = (k < 16) ? wsum[k] : 0.f;
#pragma unroll
        for (int o = 8; o > 0; o >>= 1) t += __shfl_xor_sync(0xffffffffu, t, o);
        if (k == 0) tot = t;
    }
    __syncthreads();
    float nn   = tot;
    float norm = (avg_c + EPSf) / (nn + Kk * EPSf) * nn;
    d_scale[k] = 1.f / (bias * norm);
}

// ---------------------------------------------------------------------------
// Kernel D: emit new_weight [K, D]
// ---------------------------------------------------------------------------
__global__ __launch_bounds__(256)
void weight_kernel(const float* __restrict__ ema_e,
                   const float* __restrict__ emb,
                   const int* __restrict__ training,
                   float* __restrict__ w) {
    int j = blockIdx.x * 256 + threadIdx.x;    // 0..32767 over [D, K]
    int d = j >> 9;
    int k = j & 511;

    int tr = decode_scalar_int(training);
    if (tr != 0) {
        float nhe = ema_e[j] * 0.99f + d_sums[j] * 0.01f;
        w[(k << 6) + d] = nhe * d_scale[k];
    } else {
        w[(k << 6) + d] = emb[(k << 6) + d];
    }
}

// ---------------------------------------------------------------------------
extern "C" void kernel_launch(void* const* d_in, const int* in_sizes, int n_in,
                              void* d_out, int out_size) {
    const float* x        = (const float*)d_in[0];
    const float* emb      = (const float*)d_in[1];
    const float* ema_c    = (const float*)d_in[2];
    const float* ema_e    = (const float*)d_in[3];
    const int*   counter  = (const int*)d_in[4];
    const int*   training = (const int*)d_in[5];

    float* out = (float*)d_out;
    float* q   = out;                          // [B, D, H, W]
    float* w   = out + (size_t)Bb * DHW;       // [K, D]

    const int SMEM_B = (Kk * Dd + Kk) * sizeof(float);   // 133120
    cudaFuncSetAttribute(assign_kernel, cudaFuncAttributeMaxDynamicSharedMemorySize, SMEM_B);

    prep_kernel  <<<64,  512>>>(emb);
    assign_kernel<<<256, 256, SMEM_B>>>(x, emb, q);
    norm_kernel  <<<1,   Kk>>>(ema_c, counter);
    weight_kernel<<<Dd * Kk / 256, 256>>>(ema_e, emb, training, w);
}

// round 4
// speedup vs baseline: 2.1169x; 1.4316x over previous
#include <cuda_runtime.h>
#include <math.h>
#include <stdint.h>

// Problem constants
#define Bb     32
#define Dd     64
#define Kk     512
#define DHW    262144        // D*H*W
#define Nn     131072        // B*H*W
#define EPSf   1e-5f

// ---------------------------------------------------------------------------
// Helpers
// ---------------------------------------------------------------------------
__device__ __forceinline__ uint32_t smem_to_u32(const void* p) {
    uint32_t a;
    asm("{ .reg .u64 t; cvta.to.shared.u64 t, %1; cvt.u32.u64 %0, t; }" : "=r"(a) : "l"(p));
    return a;
}
__device__ __forceinline__ void tf32_split(float v, uint32_t& hi, uint32_t& lo) {
    uint32_t h, l;
    asm("cvt.rna.tf32.f32 %0, %1;" : "=r"(h) : "f"(v));
    float r = v - __uint_as_float(h);
    asm("cvt.rna.tf32.f32 %0, %1;" : "=r"(l) : "f"(r));
    hi = h; lo = l;
}
// D = A(16x8 tf32, row) * B(8x8 tf32, col) + D, fp32 accum
__device__ __forceinline__ void mma_tf32(float* c, const uint32_t* a, uint32_t b0, uint32_t b1) {
    asm volatile("mma.sync.aligned.m16n8k8.row.col.f32.tf32.tf32.f32 "
        "{%0,%1,%2,%3}, {%4,%5,%6,%7}, {%8,%9}, {%0,%1,%2,%3};"
        : "+f"(c[0]), "+f"(c[1]), "+f"(c[2]), "+f"(c[3])
        : "r"(a[0]), "r"(a[1]), "r"(a[2]), "r"(a[3]), "r"(b0), "r"(b1));
}
#define CP_ASYNC16(s, g) asm volatile("cp.async.cg.shared.global [%0], [%1], 16;" :: "r"(s), "l"(g))
#define CP_COMMIT()      asm volatile("cp.async.commit_group;" ::: "memory")
#define CP_WAIT0()       asm volatile("cp.async.wait_group 0;" ::: "memory")

// ---------------------------------------------------------------------------
// Scratch
// ---------------------------------------------------------------------------
__device__ float d_ec[Kk];                 // ||e_k||^2
__device__ int   d_counts[Kk];
__device__ float d_sums[Dd * Kk];          // embed sums [D][K]
__device__ float d_scale[Kk];
// codebook in tf32-split mma-fragment order:
// [chunk(8)][ntile(8)][kstep(8)][lane(32)] -> {hi(d), hi(d+4), lo(d), lo(d+4)}
__device__ uint4 g_frag[32768];

// ---------------------------------------------------------------------------
// Kernel A: zero sums, counts, ||e_k||^2, tf32-split fragment packing
//   grid 64 x 512 -> 32768 threads (= Dd*Kk = frag entries)
// ---------------------------------------------------------------------------
__global__ void prep_kernel(const float* __restrict__ emb) {
    int t = threadIdx.x;
    int i = blockIdx.x * 512 + t;          // 0..32767
    d_sums[i] = 0.f;

    {   // fragment entry i
        int lane  = i & 31;
        int ks    = (i >> 5) & 7;
        int nt    = (i >> 8) & 7;
        int chunk = i >> 11;
        int code  = chunk * 64 + nt * 8 + (lane >> 2);
        int d     = ks * 8 + (lane & 3);
        float v0 = __ldg(emb + code * 64 + d);
        float v1 = __ldg(emb + code * 64 + d + 4);
        uint32_t h0, l0, h1, l1;
        tf32_split(v0, h0, l0);
        tf32_split(v1, h1, l1);
        g_frag[i] = make_uint4(h0, h1, l0, l1);
    }

    if (blockIdx.x == 0) {
        d_counts[t] = 0;
        const float4* r = (const float4*)(emb + (t << 6));
        float s = 0.f;
#pragma unroll
        for (int j = 0; j < 16; j++) {
            float4 v = __ldg(r + j);
            s += v.x * v.x + v.y * v.y + v.z * v.z + v.w * v.w;
        }
        d_ec[t] = s;
    }
}

// ---------------------------------------------------------------------------
// SMEM layout for assign kernel (bytes)
// ---------------------------------------------------------------------------
#define SM_X      0                     // 128 x 65 f32 (padded)   33280
#define SM_EC     33280                 // 512 f32                  2048
#define SM_SIDX   35328                 // 128 i32                   512
#define SM_FRAG   35840                 // 2 x 32 KB double buffer 65536
#define SM_TOTAL  101376

// ---------------------------------------------------------------------------
// Kernel B: 3xTF32 mma.sync distance GEMM + in-register argmin + outputs
//   1024 CTAs x 256 threads; CTA = 128 rows x all 512 codes
// ---------------------------------------------------------------------------
__global__ __launch_bounds__(256, 2)
void assign_kernel(const float* __restrict__ x,
                   const float* __restrict__ emb,
                   float* __restrict__ q) {
    extern __shared__ char smem[];
    uint32_t sb = smem_to_u32(smem);
    int tid = threadIdx.x;
    int wid = tid >> 5;
    int lid = tid & 31;
    int grp = lid >> 2;        // 0..7
    int tig = lid & 3;         // 0..3

    float* sx  = (float*)(smem + SM_X);
    float* sec = (float*)(smem + SM_EC);
    int*  sidx = (int*)(smem + SM_SIDX);

    // kick off chunk 0 B-fragment load immediately (overlaps x staging)
    {
        const char* src = (const char*)g_frag + tid * 16;
        uint32_t    dst = sb + SM_FRAG + tid * 16;
#pragma unroll
        for (int j = 0; j < 8; j++)
            CP_ASYNC16(dst + j * 4096, src + j * 4096);
        CP_COMMIT();
    }

    int b   = blockIdx.x >> 5;
    int hw0 = (blockIdx.x & 31) << 7;
    const float* xb = x + (size_t)b * DHW + hw0;

    // stage x tile [128 rows x 64 d], coalesced, padded smem
    for (int i = tid; i < 8192; i += 256) {
        int d = i >> 7, r = i & 127;
        sx[r * 65 + d] = __ldg(xb + (d << 12) + r);
    }
    sec[tid]       = d_ec[tid];
    sec[tid + 256] = d_ec[tid + 256];
    __syncthreads();

    // A fragments (16 rows per warp, full D=64, tf32 hi+lo) -> registers
    uint32_t Ahi[32], Alo[32];
    int r0 = (wid << 4) + grp;
#pragma unroll
    for (int ks = 0; ks < 8; ks++) {
        float v00 = sx[r0 * 65 + ks * 8 + tig];
        float v10 = sx[(r0 + 8) * 65 + ks * 8 + tig];
        float v01 = sx[r0 * 65 + ks * 8 + tig + 4];
        float v11 = sx[(r0 + 8) * 65 + ks * 8 + tig + 4];
        tf32_split(v00, Ahi[ks * 4 + 0], Alo[ks * 4 + 0]);
        tf32_split(v10, Ahi[ks * 4 + 1], Alo[ks * 4 + 1]);
        tf32_split(v01, Ahi[ks * 4 + 2], Alo[ks * 4 + 2]);
        tf32_split(v11, Ahi[ks * 4 + 3], Alo[ks * 4 + 3]);
    }

    float best0 = 3.4e38f, best1 = 3.4e38f;
    int   idx0 = 0, idx1 = 0;

    for (int c = 0; c < 8; c++) {
        CP_WAIT0();
        __syncthreads();
        if (c < 7) {   // prefetch next chunk into other buffer
            const char* src = (const char*)g_frag + (c + 1) * 32768 + tid * 16;
            uint32_t    dst = sb + SM_FRAG + ((c + 1) & 1) * 32768 + tid * 16;
#pragma unroll
            for (int j = 0; j < 8; j++)
                CP_ASYNC16(dst + j * 4096, src + j * 4096);
            CP_COMMIT();
        }

        uint32_t fb = sb + SM_FRAG + (c & 1) * 32768;
#pragma unroll
        for (int np = 0; np < 4; np++) {           // two n-tiles per iter
            float acc0[4] = {0.f, 0.f, 0.f, 0.f};
            float acc1[4] = {0.f, 0.f, 0.f, 0.f};
#pragma unroll
            for (int ks = 0; ks < 8; ks++) {
                uint32_t a0 = fb + ((((2 * np) * 8 + ks) * 32 + lid) << 4);
                uint4 bA, bB;
                asm volatile("ld.shared.v4.b32 {%0,%1,%2,%3}, [%4];"
                    : "=r"(bA.x), "=r"(bA.y), "=r"(bA.z), "=r"(bA.w) : "r"(a0));
                asm volatile("ld.shared.v4.b32 {%0,%1,%2,%3}, [%4];"
                    : "=r"(bB.x), "=r"(bB.y), "=r"(bB.z), "=r"(bB.w) : "r"(a0 + 4096));
                const uint32_t* ah = &Ahi[ks * 4];
                const uint32_t* al = &Alo[ks * 4];
                mma_tf32(acc0, ah, bA.x, bA.y);    // hi*hi
                mma_tf32(acc1, ah, bB.x, bB.y);
                mma_tf32(acc0, ah, bA.z, bA.w);    // hi*lo
                mma_tf32(acc1, ah, bB.z, bB.w);
                mma_tf32(acc0, al, bA.x, bA.y);    // lo*hi
                mma_tf32(acc1, al, bB.x, bB.y);
            }
            // scores + running argmin (cols ascending -> strict < keeps first)
            int base0 = c * 64 + (2 * np) * 8 + 2 * tig;
            float2 e0 = *(float2*)(sec + base0);
            float2 e1 = *(float2*)(sec + base0 + 8);
            float s;
            s = fmaf(acc0[0], -2.f, e0.x); if (s < best0) { best0 = s; idx0 = base0; }
            s = fmaf(acc0[1], -2.f, e0.y); if (s < best0) { best0 = s; idx0 = base0 + 1; }
            s = fmaf(acc1[0], -2.f, e1.x); if (s < best0) { best0 = s; idx0 = base0 + 8; }
            s = fmaf(acc1[1], -2.f, e1.y); if (s < best0) { best0 = s; idx0 = base0 + 9; }
            s = fmaf(acc0[2], -2.f, e0.x); if (s < best1) { best1 = s; idx1 = base0; }
            s = fmaf(acc0[3], -2.f, e0.y); if (s < best1) { best1 = s; idx1 = base0 + 1; }
            s = fmaf(acc1[2], -2.f, e1.x); if (s < best1) { best1 = s; idx1 = base0 + 8; }
            s = fmaf(acc1[3], -2.f, e1.y); if (s < best1) { best1 = s; idx1 = base0 + 9; }
        }
    }

    // reduce argmin across the 4 threads of each group (tie -> lowest index)
#pragma unroll
    for (int o = 1; o <= 2; o <<= 1) {
        float ob = __shfl_xor_sync(0xffffffffu, best0, o);
        int   oi = __shfl_xor_sync(0xffffffffu, idx0, o);
        if (ob < best0 || (ob == best0 && oi < idx0)) { best0 = ob; idx0 = oi; }
        ob = __shfl_xor_sync(0xffffffffu, best1, o);
        oi = __shfl_xor_sync(0xffffffffu, idx1, o);
        if (ob < best1 || (ob == best1 && oi < idx1)) { best1 = ob; idx1 = oi; }
    }
    if (tig == 0) { sidx[r0] = idx0; sidx[r0 + 8] = idx1; }
    __syncthreads();

    // outputs: q rows (from L2-resident emb), counts, fused EMA sums
    {
        int r  = tid >> 1;
        int d0 = (tid & 1) << 5;
        int ki = sidx[r];
        if ((tid & 1) == 0) atomicAdd(&d_counts[ki], 1);
        const float* er = emb + (ki << 6);
        float* op = q + (size_t)b * DHW + hw0 + r;
#pragma unroll 8
        for (int j = 0; j < 32; j++) {
            int d = d0 + j;
            op[d << 12] = __ldg(er + d);
            atomicAdd(&d_sums[(d << 9) + ki], sx[r * 65 + d]);
        }
    }
}

// ---------------------------------------------------------------------------
// Kernel C: counts EMA -> norm factor (single CTA)
// ---------------------------------------------------------------------------
__device__ __forceinline__ int decode_scalar_int(const int* p) {
    int v = *p;
    if (v >= 0 && v < 1000000) return v;
    return (int)__int_as_float(v);
}

__global__ void norm_kernel(const float* __restrict__ ema_c,
                            const int* __restrict__ counter) {
    __shared__ float wsum[16];
    __shared__ float tot;
    int k = threadIdx.x;

    int   cnt  = decode_scalar_int(counter) + 1;
    float bias = 1.f - (float)pow(0.99, (double)cnt);

    float avg_c = (ema_c[k] * 0.99f + (float)d_counts[k] * 0.01f) / bias;

    float s = avg_c;
#pragma unroll
    for (int o = 16; o > 0; o >>= 1) s += __shfl_xor_sync(0xffffffffu, s, o);
    if ((k & 31) == 0) wsum[k >> 5] = s;
    __syncthreads();
    if (k < 32) {
        float t = (k < 16) ? wsum[k] : 0.f;
#pragma unroll
        for (int o = 8; o > 0; o >>= 1) t += __shfl_xor_sync(0xffffffffu, t, o);
        if (k == 0) tot = t;
    }
    __syncthreads();
    float nn   = tot;
    float norm = (avg_c + EPSf) / (nn + Kk * EPSf) * nn;
    d_scale[k] = 1.f / (bias * norm);
}

// ---------------------------------------------------------------------------
// Kernel D: emit new_weight [K, D]
// ---------------------------------------------------------------------------
__global__ __launch_bounds__(256)
void weight_kernel(const float* __restrict__ ema_e,
                   const float* __restrict__ emb,
                   const int* __restrict__ training,
                   float* __restrict__ w) {
    int j = blockIdx.x * 256 + threadIdx.x;    // over [D, K]
    int d = j >> 9;
    int k = j & 511;

    int tr = decode_scalar_int(training);
    if (tr != 0) {
        float nhe = ema_e[j] * 0.99f + d_sums[j] * 0.01f;
        w[(k << 6) + d] = nhe * d_scale[k];
    } else {
        w[(k << 6) + d] = emb[(k << 6) + d];
    }
}

// ---------------------------------------------------------------------------
extern "C" void kernel_launch(void* const* d_in, const int* in_sizes, int n_in,
                              void* d_out, int out_size) {
    const float* x        = (const float*)d_in[0];
    const float* emb      = (const float*)d_in[1];
    const float* ema_c    = (const float*)d_in[2];
    const float* ema_e    = (const float*)d_in[3];
    const int*   counter  = (const int*)d_in[4];
    const int*   training = (const int*)d_in[5];

    float* out = (float*)d_out;
    float* q   = out;                          // [B, D, H, W]
    float* w   = out + (size_t)Bb * DHW;       // [K, D]

    cudaFuncSetAttribute(assign_kernel, cudaFuncAttributeMaxDynamicSharedMemorySize, SM_TOTAL);

    prep_kernel  <<<64,   512>>>(emb);
    assign_kernel<<<1024, 256, SM_TOTAL>>>(x, emb, q);
    norm_kernel  <<<1,    Kk>>>(ema_c, counter);
    weight_kernel<<<Dd * Kk / 256, 256>>>(ema_e, emb, training, w);
}

// round 5
// speedup vs baseline: 2.9590x; 1.3978x over previous
#include <cuda_runtime.h>
#include <cuda_fp16.h>
#include <math.h>
#include <stdint.h>

// Problem constants
#define Bb     32
#define Dd     64
#define Kk     512
#define DHW    262144        // D*H*W
#define Nn     131072        // B*H*W
#define EPSf   1e-5f

// ---------------------------------------------------------------------------
// Helpers
// ---------------------------------------------------------------------------
__device__ __forceinline__ uint32_t smem_to_u32(const void* p) {
    uint32_t a;
    asm("{ .reg .u64 t; cvta.to.shared.u64 t, %1; cvt.u32.u64 %0, t; }" : "=r"(a) : "l"(p));
    return a;
}
// fp16 split of a pair of floats: hi = h2(fp16(a), fp16(b)), lo = h2 of residuals
__device__ __forceinline__ void f16_split2(float a, float b, uint32_t& hi, uint32_t& lo) {
    __half ha = __float2half_rn(a), hb = __float2half_rn(b);
    float  ra = a - __half2float(ha), rb = b - __half2float(hb);
    __half la = __float2half_rn(ra), lb = __float2half_rn(rb);
    __half2 h = __halves2half2(ha, hb), l = __halves2half2(la, lb);
    hi = *(uint32_t*)&h;
    lo = *(uint32_t*)&l;
}
// D = A(16x16 f16, row) * B(16x8 f16, col) + D, fp32 accum
__device__ __forceinline__ void mma_f16(float* c, const uint32_t* a, uint32_t b0, uint32_t b1) {
    asm volatile("mma.sync.aligned.m16n8k16.row.col.f32.f16.f16.f32 "
        "{%0,%1,%2,%3}, {%4,%5,%6,%7}, {%8,%9}, {%0,%1,%2,%3};"
        : "+f"(c[0]), "+f"(c[1]), "+f"(c[2]), "+f"(c[3])
        : "r"(a[0]), "r"(a[1]), "r"(a[2]), "r"(a[3]), "r"(b0), "r"(b1));
}
#define CP_ASYNC16(s, g) asm volatile("cp.async.cg.shared.global [%0], [%1], 16;" :: "r"(s), "l"(g))
#define CP_COMMIT()      asm volatile("cp.async.commit_group;" ::: "memory")
#define CP_WAIT0()       asm volatile("cp.async.wait_group 0;" ::: "memory")

// ---------------------------------------------------------------------------
// Scratch
// ---------------------------------------------------------------------------
__device__ float d_ec[Kk];                 // ||e_k||^2
__device__ int   d_counts[Kk];
__device__ float d_sums[Dd * Kk];          // embed sums [D][K]
__device__ float d_scale[Kk];
// codebook in fp16-split mma-fragment order:
// [chunk(8)][ntile(8)][kstep(4)][lane(32)] -> {b0hi, b1hi, b0lo, b1lo}
__device__ uint4 g_frag[8192];

// ---------------------------------------------------------------------------
// Kernel A: zero sums/counts, ||e_k||^2, fp16-split fragment packing
//   grid 64 x 512
// ---------------------------------------------------------------------------
__global__ void prep_kernel(const float* __restrict__ emb) {
    int t = threadIdx.x;
    int i = blockIdx.x * 512 + t;          // 0..32767
    d_sums[i] = 0.f;

    if (i < 8192) {   // fragment entry i
        int lane  = i & 31;
        int ks    = (i >> 5) & 3;
        int nt    = (i >> 7) & 7;
        int chunk = i >> 10;
        int code  = chunk * 64 + nt * 8 + (lane >> 2);
        int k0    = ks * 16 + (lane & 3) * 2;
        const float* er = emb + code * 64 + k0;
        float v00 = __ldg(er),     v01 = __ldg(er + 1);
        float v10 = __ldg(er + 8), v11 = __ldg(er + 9);
        uint32_t h0, l0, h1, l1;
        f16_split2(v00, v01, h0, l0);
        f16_split2(v10, v11, h1, l1);
        g_frag[i] = make_uint4(h0, h1, l0, l1);
    }

    if (blockIdx.x == 0) {
        d_counts[t] = 0;
        const float4* r = (const float4*)(emb + (t << 6));
        float s = 0.f;
#pragma unroll
        for (int j = 0; j < 16; j++) {
            float4 v = __ldg(r + j);
            s += v.x * v.x + v.y * v.y + v.z * v.z + v.w * v.w;
        }
        d_ec[t] = s;
    }
}

// ---------------------------------------------------------------------------
// SMEM layout for assign kernel (bytes)
// ---------------------------------------------------------------------------
#define SM_X      0                     // 128 x 65 f32 (padded)   33280
#define SM_EC     33280                 // 512 f32                  2048
#define SM_SIDX   35328                 // 128 i32                   512
#define SM_FRAG   35840                 // 2 x 16 KB double buffer 32768
#define SM_TOTAL  68608

// ---------------------------------------------------------------------------
// Kernel B: 3xFP16 mma.sync(m16n8k16) distance GEMM + in-register argmin
//   1024 CTAs x 256 threads; CTA = 128 rows x all 512 codes
// ---------------------------------------------------------------------------
__global__ __launch_bounds__(256, 2)
void assign_kernel(const float* __restrict__ x,
                   const float* __restrict__ emb,
                   float* __restrict__ q) {
    extern __shared__ char smem[];
    uint32_t sb = smem_to_u32(smem);
    int tid = threadIdx.x;
    int wid = tid >> 5;
    int lid = tid & 31;
    int grp = lid >> 2;        // 0..7
    int tig = lid & 3;         // 0..3

    float* sx  = (float*)(smem + SM_X);
    float* sec = (float*)(smem + SM_EC);
    int*  sidx = (int*)(smem + SM_SIDX);

    // kick off chunk 0 B-fragment load immediately (overlaps x staging)
    {
        const char* src = (const char*)g_frag + tid * 16;
        uint32_t    dst = sb + SM_FRAG + tid * 16;
#pragma unroll
        for (int j = 0; j < 4; j++)
            CP_ASYNC16(dst + j * 4096, src + j * 4096);
        CP_COMMIT();
    }

    int b   = blockIdx.x >> 5;
    int hw0 = (blockIdx.x & 31) << 7;
    const float* xb = x + (size_t)b * DHW + hw0;

    // stage x tile [128 rows x 64 d], coalesced, padded smem
    for (int i = tid; i < 8192; i += 256) {
        int d = i >> 7, r = i & 127;
        sx[r * 65 + d] = __ldg(xb + (d << 12) + r);
    }
    sec[tid]       = d_ec[tid];
    sec[tid + 256] = d_ec[tid + 256];
    __syncthreads();

    // A fragments (16 rows per warp, full D=64, fp16 hi+lo) -> 32 regs
    uint32_t Ahi[16], Alo[16];
    int r0 = (wid << 4) + grp;
#pragma unroll
    for (int ks = 0; ks < 4; ks++) {
        int kb = ks * 16, c0 = tig * 2;
        f16_split2(sx[r0 * 65 + kb + c0],           sx[r0 * 65 + kb + c0 + 1],
                   Ahi[ks * 4 + 0], Alo[ks * 4 + 0]);
        f16_split2(sx[(r0 + 8) * 65 + kb + c0],     sx[(r0 + 8) * 65 + kb + c0 + 1],
                   Ahi[ks * 4 + 1], Alo[ks * 4 + 1]);
        f16_split2(sx[r0 * 65 + kb + c0 + 8],       sx[r0 * 65 + kb + c0 + 9],
                   Ahi[ks * 4 + 2], Alo[ks * 4 + 2]);
        f16_split2(sx[(r0 + 8) * 65 + kb + c0 + 8], sx[(r0 + 8) * 65 + kb + c0 + 9],
                   Ahi[ks * 4 + 3], Alo[ks * 4 + 3]);
    }

    float best0 = 3.4e38f, best1 = 3.4e38f;
    int   idx0 = 0, idx1 = 0;

    for (int c = 0; c < 8; c++) {
        CP_WAIT0();
        __syncthreads();
        if (c < 7) {   // prefetch next chunk into other buffer
            const char* src = (const char*)g_frag + (c + 1) * 16384 + tid * 16;
            uint32_t    dst = sb + SM_FRAG + ((c + 1) & 1) * 16384 + tid * 16;
#pragma unroll
            for (int j = 0; j < 4; j++)
                CP_ASYNC16(dst + j * 4096, src + j * 4096);
            CP_COMMIT();
        }

        uint32_t fb = sb + SM_FRAG + (c & 1) * 16384;
#pragma unroll
        for (int np = 0; np < 4; np++) {           // two n-tiles per iter
            float acc0[4] = {0.f, 0.f, 0.f, 0.f};
            float acc1[4] = {0.f, 0.f, 0.f, 0.f};
#pragma unroll
            for (int ks = 0; ks < 4; ks++) {
                uint32_t a0 = fb + ((((2 * np) * 4 + ks) * 32 + lid) << 4);
                uint4 bA, bB;
                asm volatile("ld.shared.v4.b32 {%0,%1,%2,%3}, [%4];"
                    : "=r"(bA.x), "=r"(bA.y), "=r"(bA.z), "=r"(bA.w) : "r"(a0));
                asm volatile("ld.shared.v4.b32 {%0,%1,%2,%3}, [%4];"
                    : "=r"(bB.x), "=r"(bB.y), "=r"(bB.z), "=r"(bB.w) : "r"(a0 + 2048));
                const uint32_t* ah = &Ahi[ks * 4];
                const uint32_t* al = &Alo[ks * 4];
                mma_f16(acc0, ah, bA.x, bA.y);     // hi*hi
                mma_f16(acc1, ah, bB.x, bB.y);
                mma_f16(acc0, ah, bA.z, bA.w);     // hi*lo
                mma_f16(acc1, ah, bB.z, bB.w);
                mma_f16(acc0, al, bA.x, bA.y);     // lo*hi
                mma_f16(acc1, al, bB.x, bB.y);
            }
            // scores + running argmin (cols ascending -> strict < keeps first)
            int base0 = c * 64 + (2 * np) * 8 + 2 * tig;
            float2 e0 = *(float2*)(sec + base0);
            float2 e1 = *(float2*)(sec + base0 + 8);
            float s;
            s = fmaf(acc0[0], -2.f, e0.x); if (s < best0) { best0 = s; idx0 = base0; }
            s = fmaf(acc0[1], -2.f, e0.y); if (s < best0) { best0 = s; idx0 = base0 + 1; }
            s = fmaf(acc1[0], -2.f, e1.x); if (s < best0) { best0 = s; idx0 = base0 + 8; }
            s = fmaf(acc1[1], -2.f, e1.y); if (s < best0) { best0 = s; idx0 = base0 + 9; }
            s = fmaf(acc0[2], -2.f, e0.x); if (s < best1) { best1 = s; idx1 = base0; }
            s = fmaf(acc0[3], -2.f, e0.y); if (s < best1) { best1 = s; idx1 = base0 + 1; }
            s = fmaf(acc1[2], -2.f, e1.x); if (s < best1) { best1 = s; idx1 = base0 + 8; }
            s = fmaf(acc1[3], -2.f, e1.y); if (s < best1) { best1 = s; idx1 = base0 + 9; }
        }
    }

    // reduce argmin across the 4 threads of each group (tie -> lowest index)
#pragma unroll
    for (int o = 1; o <= 2; o <<= 1) {
        float ob = __shfl_xor_sync(0xffffffffu, best0, o);
        int   oi = __shfl_xor_sync(0xffffffffu, idx0, o);
        if (ob < best0 || (ob == best0 && oi < idx0)) { best0 = ob; idx0 = oi; }
        ob = __shfl_xor_sync(0xffffffffu, best1, o);
        oi = __shfl_xor_sync(0xffffffffu, idx1, o);
        if (ob < best1 || (ob == best1 && oi < idx1)) { best1 = ob; idx1 = oi; }
    }
    if (tig == 0) { sidx[r0] = idx0; sidx[r0 + 8] = idx1; }
    __syncthreads();

    // outputs: q rows (from L2-resident emb), counts, fused EMA sums
    {
        int r  = tid >> 1;
        int d0 = (tid & 1) << 5;
        int ki = sidx[r];
        if ((tid & 1) == 0) atomicAdd(&d_counts[ki], 1);
        const float* er = emb + (ki << 6);
        float* op = q + (size_t)b * DHW + hw0 + r;
#pragma unroll 8
        for (int j = 0; j < 32; j++) {
            int d = d0 + j;
            op[d << 12] = __ldg(er + d);
            atomicAdd(&d_sums[(d << 9) + ki], sx[r * 65 + d]);
        }
    }
}

// ---------------------------------------------------------------------------
// Kernel C: counts EMA -> norm factor (single CTA)
// ---------------------------------------------------------------------------
__device__ __forceinline__ int decode_scalar_int(const int* p) {
    int v = *p;
    if (v >= 0 && v < 1000000) return v;
    return (int)__int_as_float(v);
}

__global__ void norm_kernel(const float* __restrict__ ema_c,
                            const int* __restrict__ counter) {
    __shared__ float wsum[16];
    __shared__ float tot;
    int k = threadIdx.x;

    int   cnt  = decode_scalar_int(counter) + 1;
    float bias = 1.f - (float)pow(0.99, (double)cnt);

    float avg_c = (ema_c[k] * 0.99f + (float)d_counts[k] * 0.01f) / bias;

    float s = avg_c;
#pragma unroll
    for (int o = 16; o > 0; o >>= 1) s += __shfl_xor_sync(0xffffffffu, s, o);
    if ((k & 31) == 0) wsum[k >> 5] = s;
    __syncthreads();
    if (k < 32) {
        float t = (k < 16) ? wsum[k] : 0.f;
#pragma unroll
        for (int o = 8; o > 0; o >>= 1) t += __shfl_xor_sync(0xffffffffu, t, o);
        if (k == 0) tot = t;
    }
    __syncthreads();
    float nn   = tot;
    float norm = (avg_c + EPSf) / (nn + Kk * EPSf) * nn;
    d_scale[k] = 1.f / (bias * norm);
}

// ---------------------------------------------------------------------------
// Kernel D: emit new_weight [K, D]
// ---------------------------------------------------------------------------
__global__ __launch_bounds__(256)
void weight_kernel(const float* __restrict__ ema_e,
                   const float* __restrict__ emb,
                   const int* __restrict__ training,
                   float* __restrict__ w) {
    int j = blockIdx.x * 256 + threadIdx.x;    // over [D, K]
    int d = j >> 9;
    int k = j & 511;

    int tr = decode_scalar_int(training);
    if (tr != 0) {
        float nhe = ema_e[j] * 0.99f + d_sums[j] * 0.01f;
        w[(k << 6) + d] = nhe * d_scale[k];
    } else {
        w[(k << 6) + d] = emb[(k << 6) + d];
    }
}

// ---------------------------------------------------------------------------
extern "C" void kernel_launch(void* const* d_in, const int* in_sizes, int n_in,
                              void* d_out, int out_size) {
    const float* x        = (const float*)d_in[0];
    const float* emb      = (const float*)d_in[1];
    const float* ema_c    = (const float*)d_in[2];
    const float* ema_e    = (const float*)d_in[3];
    const int*   counter  = (const int*)d_in[4];
    const int*   training = (const int*)d_in[5];

    float* out = (float*)d_out;
    float* q   = out;                          // [B, D, H, W]
    float* w   = out + (size_t)Bb * DHW;       // [K, D]

    cudaFuncSetAttribute(assign_kernel, cudaFuncAttributeMaxDynamicSharedMemorySize, SM_TOTAL);

    prep_kernel  <<<64,   512>>>(emb);
    assign_kernel<<<1024, 256, SM_TOTAL>>>(x, emb, q);
    norm_kernel  <<<1,    Kk>>>(ema_c, counter);
    weight_kernel<<<Dd * Kk / 256, 256>>>(ema_e, emb, training, w);
}

// round 6
// speedup vs baseline: 2.9814x; 1.0075x over previous
#include <cuda_runtime.h>
#include <cuda_fp16.h>
#include <math.h>
#include <stdint.h>

// Problem constants
#define Bb     32
#define Dd     64
#define Kk     512
#define DHW    262144        // D*H*W
#define Nn     131072        // B*H*W
#define EPSf   1e-5f
#define NTILES 1024          // 128-row tiles
#define GRID_P 148           // persistent CTAs

// ---------------------------------------------------------------------------
// Helpers
// ---------------------------------------------------------------------------
__device__ __forceinline__ uint32_t smem_to_u32(const void* p) {
    uint32_t a;
    asm("{ .reg .u64 t; cvta.to.shared.u64 t, %1; cvt.u32.u64 %0, t; }" : "=r"(a) : "l"(p));
    return a;
}
// fp16 split of a pair of floats: hi = h2(fp16(a), fp16(b)), lo = h2 of residuals
__device__ __forceinline__ void f16_split2(float a, float b, uint32_t& hi, uint32_t& lo) {
    __half ha = __float2half_rn(a), hb = __float2half_rn(b);
    float  ra = a - __half2float(ha), rb = b - __half2float(hb);
    __half la = __float2half_rn(ra), lb = __float2half_rn(rb);
    __half2 h = __halves2half2(ha, hb), l = __halves2half2(la, lb);
    hi = *(uint32_t*)&h;
    lo = *(uint32_t*)&l;
}
// D = A(16x16 f16, row) * B(16x8 f16, col) + D, fp32 accum
__device__ __forceinline__ void mma_f16(float* c, const uint32_t* a, uint32_t b0, uint32_t b1) {
    asm volatile("mma.sync.aligned.m16n8k16.row.col.f32.f16.f16.f32 "
        "{%0,%1,%2,%3}, {%4,%5,%6,%7}, {%8,%9}, {%0,%1,%2,%3};"
        : "+f"(c[0]), "+f"(c[1]), "+f"(c[2]), "+f"(c[3])
        : "r"(a[0]), "r"(a[1]), "r"(a[2]), "r"(a[3]), "r"(b0), "r"(b1));
}
#define CP_ASYNC16(s, g) asm volatile("cp.async.cg.shared.global [%0], [%1], 16;" :: "r"(s), "l"(g))
#define CP_COMMIT()      asm volatile("cp.async.commit_group;" ::: "memory")
#define CP_WAIT0()       asm volatile("cp.async.wait_group 0;" ::: "memory")

// ---------------------------------------------------------------------------
// Scratch
// ---------------------------------------------------------------------------
__device__ float d_ec[Kk];                 // ||e_k||^2
__device__ int   d_counts[Kk];
__device__ float d_sums[Dd * Kk];          // embed sums [D][K]
__device__ float d_scale[Kk];
// codebook in fp16-split mma-fragment order:
// [ntile(64)][kstep(4)][lane(32)] -> {b0hi, b1hi, b0lo, b1lo}
__device__ uint4 g_frag[8192];

// ---------------------------------------------------------------------------
// Kernel A: zero sums/counts, ||e_k||^2, fp16-split fragment packing
// ---------------------------------------------------------------------------
__global__ void prep_kernel(const float* __restrict__ emb) {
    int t = threadIdx.x;
    int i = blockIdx.x * 512 + t;          // 0..32767
    d_sums[i] = 0.f;

    if (i < 8192) {   // fragment entry i
        int lane = i & 31;
        int ks   = (i >> 5) & 3;
        int nt   = i >> 7;                 // 0..63
        int code = nt * 8 + (lane >> 2);
        int k0   = ks * 16 + (lane & 3) * 2;
        const float* er = emb + code * 64 + k0;
        float v00 = __ldg(er),     v01 = __ldg(er + 1);
        float v10 = __ldg(er + 8), v11 = __ldg(er + 9);
        uint32_t h0, l0, h1, l1;
        f16_split2(v00, v01, h0, l0);
        f16_split2(v10, v11, h1, l1);
        g_frag[i] = make_uint4(h0, h1, l0, l1);
    }

    if (blockIdx.x == 0) {
        d_counts[t] = 0;
        const float4* r = (const float4*)(emb + (t << 6));
        float s = 0.f;
#pragma unroll
        for (int j = 0; j < 16; j++) {
            float4 v = __ldg(r + j);
            s += v.x * v.x + v.y * v.y + v.z * v.z + v.w * v.w;
        }
        d_ec[t] = s;
    }
}

// ---------------------------------------------------------------------------
// SMEM layout (bytes): x tiles are [d(64)][132 f32] (pad 4), double buffered
// ---------------------------------------------------------------------------
#define XLD       132
#define SM_X0     0                        // 64*132*4 = 33792
#define SM_X1     33792
#define SM_EC     67584                    // 512 f32
#define SM_BEST   69632                    // 2*128 f32
#define SM_IDXH   70656                    // 2*128 i32
#define SM_SIDX   71680                    // 128 i32
#define SM_FRAG   72192                    // 131072
#define SM_TOTAL  203264

// ---------------------------------------------------------------------------
// Kernel B: persistent 3xFP16 mma.sync GEMM, full codebook resident in SMEM
//   148 CTAs x 512 threads, occupancy 1. Warps 0-7: codes 0-255, 8-15: 256-511.
// ---------------------------------------------------------------------------
__global__ __launch_bounds__(512, 1)
void assign_kernel(const float* __restrict__ x,
                   const float* __restrict__ emb,
                   float* __restrict__ q) {
    extern __shared__ char smem[];
    uint32_t sb = smem_to_u32(smem);
    int tid = threadIdx.x;
    int wid = tid >> 5;
    int lid = tid & 31;
    int grp = lid >> 2;        // 0..7
    int tig = lid & 3;         // 0..3
    int wg  = wid >> 3;        // 0/1 code-half
    int r0  = ((wid & 7) << 4) + grp;

    float* sec   = (float*)(smem + SM_EC);
    float* sbest = (float*)(smem + SM_BEST);
    int*   sidxh = (int*)(smem + SM_IDXH);
    int*   sidx  = (int*)(smem + SM_SIDX);

    // ---- prologue: codebook fragments + ec + first x tile ----
#pragma unroll
    for (int jj = 0; jj < 16; jj++) {
        int i = tid + jj * 512;
        CP_ASYNC16(sb + SM_FRAG + i * 16, (const char*)g_frag + i * 16);
    }
    {
        int t0  = blockIdx.x;
        const float* xb = x + (size_t)(t0 >> 5) * DHW + ((t0 & 31) << 7);
#pragma unroll
        for (int jj = 0; jj < 4; jj++) {
            int i = tid + jj * 512;             // 0..2047
            int d = i >> 5, r4 = (i & 31) << 2;
            CP_ASYNC16(sb + SM_X0 + (d * XLD + r4) * 4,
                       (const char*)(xb + (d << 12) + r4));
        }
    }
    sec[tid] = d_ec[tid];
    CP_COMMIT();
    CP_WAIT0();
    __syncthreads();

    // ---- persistent tile loop ----
    int j = 0;
    for (int t = blockIdx.x; t < NTILES; t += GRID_P, j++) {
        float* sxc = (float*)(smem + ((j & 1) ? SM_X1 : SM_X0));
        float* sxn = (float*)(smem + ((j & 1) ? SM_X0 : SM_X1));
        int b   = t >> 5;
        int hw0 = (t & 31) << 7;

        // prefetch next tile (overlaps entire MMA phase)
        int tn = t + GRID_P;
        if (tn < NTILES) {
            const float* xb = x + (size_t)(tn >> 5) * DHW + ((tn & 31) << 7);
            uint32_t dstb = sb + ((j & 1) ? SM_X0 : SM_X1);
#pragma unroll
            for (int jj = 0; jj < 4; jj++) {
                int i = tid + jj * 512;
                int d = i >> 5, r4 = (i & 31) << 2;
                CP_ASYNC16(dstb + (d * XLD + r4) * 4,
                           (const char*)(xb + (d << 12) + r4));
            }
        }
        CP_COMMIT();

        // A fragments: 16 rows (r0, r0+8 x 8 groups), full D=64, fp16 hi+lo
        uint32_t Ahi[16], Alo[16];
#pragma unroll
        for (int ks = 0; ks < 4; ks++) {
            int kb = ks * 16 + tig * 2;
            f16_split2(sxc[kb * XLD + r0],           sxc[(kb + 1) * XLD + r0],
                       Ahi[ks * 4 + 0], Alo[ks * 4 + 0]);
            f16_split2(sxc[kb * XLD + r0 + 8],       sxc[(kb + 1) * XLD + r0 + 8],
                       Ahi[ks * 4 + 1], Alo[ks * 4 + 1]);
            f16_split2(sxc[(kb + 8) * XLD + r0],     sxc[(kb + 9) * XLD + r0],
                       Ahi[ks * 4 + 2], Alo[ks * 4 + 2]);
            f16_split2(sxc[(kb + 8) * XLD + r0 + 8], sxc[(kb + 9) * XLD + r0 + 8],
                       Ahi[ks * 4 + 3], Alo[ks * 4 + 3]);
        }

        float best0 = 3.4e38f, best1 = 3.4e38f;
        int   idx0 = 0, idx1 = 0;

#pragma unroll 4
        for (int np = 0; np < 16; np++) {
            int ntA = (wg << 5) + 2 * np;
            float acc0[4] = {0.f, 0.f, 0.f, 0.f};
            float acc1[4] = {0.f, 0.f, 0.f, 0.f};
#pragma unroll
            for (int ks = 0; ks < 4; ks++) {
                uint32_t a0 = sb + SM_FRAG + ((((ntA << 2) + ks) << 5) + lid) * 16;
                uint4 bA, bB;
                asm volatile("ld.shared.v4.b32 {%0,%1,%2,%3}, [%4];"
                    : "=r"(bA.x), "=r"(bA.y), "=r"(bA.z), "=r"(bA.w) : "r"(a0));
                asm volatile("ld.shared.v4.b32 {%0,%1,%2,%3}, [%4];"
                    : "=r"(bB.x), "=r"(bB.y), "=r"(bB.z), "=r"(bB.w) : "r"(a0 + 2048));
                const uint32_t* ah = &Ahi[ks * 4];
                const uint32_t* al = &Alo[ks * 4];
                mma_f16(acc0, ah, bA.x, bA.y);     // hi*hi
                mma_f16(acc1, ah, bB.x, bB.y);
                mma_f16(acc0, ah, bA.z, bA.w);     // hi*lo
                mma_f16(acc1, ah, bB.z, bB.w);
                mma_f16(acc0, al, bA.x, bA.y);     // lo*hi
                mma_f16(acc1, al, bB.x, bB.y);
            }
            int base0 = ntA * 8 + 2 * tig;
            float2 e0 = *(float2*)(sec + base0);
            float2 e1 = *(float2*)(sec + base0 + 8);
            float s;
            s = fmaf(acc0[0], -2.f, e0.x); if (s < best0) { best0 = s; idx0 = base0; }
            s = fmaf(acc0[1], -2.f, e0.y); if (s < best0) { best0 = s; idx0 = base0 + 1; }
            s = fmaf(acc1[0], -2.f, e1.x); if (s < best0) { best0 = s; idx0 = base0 + 8; }
            s = fmaf(acc1[1], -2.f, e1.y); if (s < best0) { best0 = s; idx0 = base0 + 9; }
            s = fmaf(acc0[2], -2.f, e0.x); if (s < best1) { best1 = s; idx1 = base0; }
            s = fmaf(acc0[3], -2.f, e0.y); if (s < best1) { best1 = s; idx1 = base0 + 1; }
            s = fmaf(acc1[2], -2.f, e1.x); if (s < best1) { best1 = s; idx1 = base0 + 8; }
            s = fmaf(acc1[3], -2.f, e1.y); if (s < best1) { best1 = s; idx1 = base0 + 9; }
        }

        // quad-group argmin reduce (tie -> lowest index)
#pragma unroll
        for (int o = 1; o <= 2; o <<= 1) {
            float ob = __shfl_xor_sync(0xffffffffu, best0, o);
            int   oi = __shfl_xor_sync(0xffffffffu, idx0, o);
            if (ob < best0 || (ob == best0 && oi < idx0)) { best0 = ob; idx0 = oi; }
            ob = __shfl_xor_sync(0xffffffffu, best1, o);
            oi = __shfl_xor_sync(0xffffffffu, idx1, o);
            if (ob < best1 || (ob == best1 && oi < idx1)) { best1 = ob; idx1 = oi; }
        }
        if (tig == 0) {
            sbest[wg * 128 + r0]     = best0;
            sbest[wg * 128 + r0 + 8] = best1;
            sidxh[wg * 128 + r0]     = idx0;
            sidxh[wg * 128 + r0 + 8] = idx1;
        }
        __syncthreads();
        // merge code halves (wg0 indices < wg1 -> strict < keeps lowest on tie)
        if (tid < 128)
            sidx[tid] = (sbest[128 + tid] < sbest[tid]) ? sidxh[128 + tid] : sidxh[tid];
        __syncthreads();

        // outputs: q rows, counts, fused EMA sums. 4 threads/row x 16 d.
        {
            int r  = tid >> 2;
            int d0 = (tid & 3) << 4;
            int ki = sidx[r];
            if ((tid & 3) == 0) atomicAdd(&d_counts[ki], 1);
            const float4* er4 = (const float4*)(emb + (ki << 6) + d0);
            float* op = q + (size_t)b * DHW + hw0 + r;
#pragma unroll
            for (int v = 0; v < 4; v++) {
                float4 ev = __ldg(er4 + v);
                int d = d0 + v * 4;
                op[(d)     << 12] = ev.x;
                op[(d + 1) << 12] = ev.y;
                op[(d + 2) << 12] = ev.z;
                op[(d + 3) << 12] = ev.w;
                atomicAdd(&d_sums[((d)     << 9) + ki], sxc[(d)     * XLD + r]);
                atomicAdd(&d_sums[((d + 1) << 9) + ki], sxc[(d + 1) * XLD + r]);
                atomicAdd(&d_sums[((d + 2) << 9) + ki], sxc[(d + 2) * XLD + r]);
                atomicAdd(&d_sums[((d + 3) << 9) + ki], sxc[(d + 3) * XLD + r]);
            }
        }

        CP_WAIT0();
        __syncthreads();
        (void)sxn;
    }
}

// ---------------------------------------------------------------------------
// Kernel C: counts EMA -> norm factor (single CTA)
// ---------------------------------------------------------------------------
__device__ __forceinline__ int decode_scalar_int(const int* p) {
    int v = *p;
    if (v >= 0 && v < 1000000) return v;
    return (int)__int_as_float(v);
}

__global__ void norm_kernel(const float* __restrict__ ema_c,
                            const int* __restrict__ counter) {
    __shared__ float wsum[16];
    __shared__ float tot;
    int k = threadIdx.x;

    int   cnt  = decode_scalar_int(counter) + 1;
    float bias = 1.f - (float)pow(0.99, (double)cnt);

    float avg_c = (ema_c[k] * 0.99f + (float)d_counts[k] * 0.01f) / bias;

    float s = avg_c;
#pragma unroll
    for (int o = 16; o > 0; o >>= 1) s += __shfl_xor_sync(0xffffffffu, s, o);
    if ((k & 31) == 0) wsum[k >> 5] = s;
    __syncthreads();
    if (k < 32) {
        float t = (k < 16) ? wsum[k] : 0.f;
#pragma unroll
        for (int o = 8; o > 0; o >>= 1) t += __shfl_xor_sync(0xffffffffu, t, o);
        if (k == 0) tot = t;
    }
    __syncthreads();
    float nn   = tot;
    float norm = (avg_c + EPSf) / (nn + Kk * EPSf) * nn;
    d_scale[k] = 1.f / (bias * norm);
}

// ---------------------------------------------------------------------------
// Kernel D: emit new_weight [K, D]
// ---------------------------------------------------------------------------
__global__ __launch_bounds__(256)
void weight_kernel(const float* __restrict__ ema_e,
                   const float* __restrict__ emb,
                   const int* __restrict__ training,
                   float* __restrict__ w) {
    int j = blockIdx.x * 256 + threadIdx.x;    // over [D, K]
    int d = j >> 9;
    int k = j & 511;

    int tr = decode_scalar_int(training);
    if (tr != 0) {
        float nhe = ema_e[j] * 0.99f + d_sums[j] * 0.01f;
        w[(k << 6) + d] = nhe * d_scale[k];
    } else {
        w[(k << 6) + d] = emb[(k << 6) + d];
    }
}

// ---------------------------------------------------------------------------
extern "C" void kernel_launch(void* const* d_in, const int* in_sizes, int n_in,
                              void* d_out, int out_size) {
    const float* x        = (const float*)d_in[0];
    const float* emb      = (const float*)d_in[1];
    const float* ema_c    = (const float*)d_in[2];
    const float* ema_e    = (const float*)d_in[3];
    const int*   counter  = (const int*)d_in[4];
    const int*   training = (const int*)d_in[5];

    float* out = (float*)d_out;
    float* q   = out;                          // [B, D, H, W]
    float* w   = out + (size_t)Bb * DHW;       // [K, D]

    cudaFuncSetAttribute(assign_kernel, cudaFuncAttributeMaxDynamicSharedMemorySize, SM_TOTAL);

    prep_kernel  <<<64,     512>>>(emb);
    assign_kernel<<<GRID_P, 512, SM_TOTAL>>>(x, emb, q);
    norm_kernel  <<<1,      Kk>>>(ema_c, counter);
    weight_kernel<<<Dd * Kk / 256, 256>>>(ema_e, emb, training, w);
}

// round 7
// speedup vs baseline: 3.1365x; 1.0520x over previous
#include <cuda_runtime.h>
#include <cuda_fp16.h>
#include <math.h>
#include <stdint.h>

// Problem constants
#define Bb     32
#define Dd     64
#define Kk     512
#define DHW    262144        // D*H*W
#define Nn     131072        // B*H*W
#define EPSf   1e-5f
#define NTILES 1024          // 128-row tiles
#define GRID_P 148           // persistent CTAs

// ---------------------------------------------------------------------------
// Helpers
// ---------------------------------------------------------------------------
__device__ __forceinline__ uint32_t smem_to_u32(const void* p) {
    uint32_t a;
    asm("{ .reg .u64 t; cvta.to.shared.u64 t, %1; cvt.u32.u64 %0, t; }" : "=r"(a) : "l"(p));
    return a;
}
// fp16 split of a pair of floats: hi = h2(fp16(a), fp16(b)), lo = h2 of residuals
__device__ __forceinline__ void f16_split2(float a, float b, uint32_t& hi, uint32_t& lo) {
    __half ha = __float2half_rn(a), hb = __float2half_rn(b);
    float  ra = a - __half2float(ha), rb = b - __half2float(hb);
    __half la = __float2half_rn(ra), lb = __float2half_rn(rb);
    __half2 h = __halves2half2(ha, hb), l = __halves2half2(la, lb);
    hi = *(uint32_t*)&h;
    lo = *(uint32_t*)&l;
}
// D = A(16x16 f16, row) * B(16x8 f16, col) + D, fp32 accum
__device__ __forceinline__ void mma_f16(float* c, const uint32_t* a, uint32_t b0, uint32_t b1) {
    asm volatile("mma.sync.aligned.m16n8k16.row.col.f32.f16.f16.f32 "
        "{%0,%1,%2,%3}, {%4,%5,%6,%7}, {%8,%9}, {%0,%1,%2,%3};"
        : "+f"(c[0]), "+f"(c[1]), "+f"(c[2]), "+f"(c[3])
        : "r"(a[0]), "r"(a[1]), "r"(a[2]), "r"(a[3]), "r"(b0), "r"(b1));
}
#define CP_ASYNC16(s, g) asm volatile("cp.async.cg.shared.global [%0], [%1], 16;" :: "r"(s), "l"(g))
#define CP_COMMIT()      asm volatile("cp.async.commit_group;" ::: "memory")
#define CP_WAIT0()       asm volatile("cp.async.wait_group 0;" ::: "memory")

// ---------------------------------------------------------------------------
// Scratch
// ---------------------------------------------------------------------------
__device__ float d_ec[Kk];                 // ||e_k||^2
__device__ int   d_counts[Kk];
__device__ float d_sums[Dd * Kk];          // embed sums [D][K]
__device__ float d_scale[Kk];
// codebook in fp16-split mma-fragment order:
// [ntile(64)][kstep(4)][lane(32)] -> {b0hi, b1hi, b0lo, b1lo}
__device__ uint4 g_frag[8192];

// ---------------------------------------------------------------------------
// Kernel A: zero sums/counts, ||e_k||^2, fp16-split fragment packing
// ---------------------------------------------------------------------------
__global__ void prep_kernel(const float* __restrict__ emb) {
    int t = threadIdx.x;
    int i = blockIdx.x * 512 + t;          // 0..32767
    d_sums[i] = 0.f;

    if (i < 8192) {   // fragment entry i
        int lane = i & 31;
        int ks   = (i >> 5) & 3;
        int nt   = i >> 7;                 // 0..63
        int code = nt * 8 + (lane >> 2);
        int k0   = ks * 16 + (lane & 3) * 2;
        const float* er = emb + code * 64 + k0;
        float v00 = __ldg(er),     v01 = __ldg(er + 1);
        float v10 = __ldg(er + 8), v11 = __ldg(er + 9);
        uint32_t h0, l0, h1, l1;
        f16_split2(v00, v01, h0, l0);
        f16_split2(v10, v11, h1, l1);
        g_frag[i] = make_uint4(h0, h1, l0, l1);
    }

    if (blockIdx.x == 0) {
        d_counts[t] = 0;
        const float4* r = (const float4*)(emb + (t << 6));
        float s = 0.f;
#pragma unroll
        for (int j = 0; j < 16; j++) {
            float4 v = __ldg(r + j);
            s += v.x * v.x + v.y * v.y + v.z * v.z + v.w * v.w;
        }
        d_ec[t] = s;
    }
}

// ---------------------------------------------------------------------------
// SMEM layout (bytes): x tiles [d(64)][132 f32], double buffered
// ---------------------------------------------------------------------------
#define XLD       132
#define SM_X0     0                        // 33792
#define SM_X1     33792                    // 33792
#define SM_EC     67584                    // 2048
#define SM_BEST   69632                    // 4*128 f32 = 2048
#define SM_IDXH   71680                    // 4*128 i32 = 2048
#define SM_SIDX   73728                    // 128 i32 -> 512
#define SM_SQ     74240                    // 128*37 f32 = 18944
#define SM_FRAG   93184                    // 131072
#define SM_TOTAL  224256

// ---------------------------------------------------------------------------
// Kernel B: persistent 3xFP16 mma.sync GEMM, codebook resident in SMEM.
//   148 CTAs x 512 threads. Warp = 32 rows x 128 codes:
//   quarter = wid & 3 (code quarter), rowset = wid >> 2 (32-row set).
// ---------------------------------------------------------------------------
__global__ __launch_bounds__(512, 1)
void assign_kernel(const float* __restrict__ x,
                   const float* __restrict__ emb,
                   float* __restrict__ q) {
    extern __shared__ char smem[];
    uint32_t sb = smem_to_u32(smem);
    int tid = threadIdx.x;
    int wid = tid >> 5;
    int lid = tid & 31;
    int grp = lid >> 2;        // 0..7
    int tig = lid & 3;         // 0..3
    int qtr = wid & 3;         // code quarter
    int rws = wid >> 2;        // row set (0..3), rows [rws*32, rws*32+32)

    float* sec   = (float*)(smem + SM_EC);
    float* sbest = (float*)(smem + SM_BEST);
    int*   sidxh = (int*)(smem + SM_IDXH);
    int*   sidx  = (int*)(smem + SM_SIDX);
    float* sq    = (float*)(smem + SM_SQ);

    // ---- prologue: codebook fragments + ec + first x tile ----
#pragma unroll
    for (int jj = 0; jj < 16; jj++) {
        int i = tid + jj * 512;
        CP_ASYNC16(sb + SM_FRAG + i * 16, (const char*)g_frag + i * 16);
    }
    {
        int t0  = blockIdx.x;
        const float* xb = x + (size_t)(t0 >> 5) * DHW + ((t0 & 31) << 7);
#pragma unroll
        for (int jj = 0; jj < 4; jj++) {
            int i = tid + jj * 512;             // 0..2047
            int d = i >> 5, r4 = (i & 31) << 2;
            CP_ASYNC16(sb + SM_X0 + (d * XLD + r4) * 4,
                       (const char*)(xb + (d << 12) + r4));
        }
    }
    sec[tid] = d_ec[tid];
    CP_COMMIT();
    CP_WAIT0();
    __syncthreads();

    // ---- persistent tile loop ----
    int j = 0;
    for (int t = blockIdx.x; t < NTILES; t += GRID_P, j++) {
        float* sxc = (float*)(smem + ((j & 1) ? SM_X1 : SM_X0));
        int b   = t >> 5;
        int hw0 = (t & 31) << 7;

        // prefetch next tile (overlaps MMA phase)
        int tn = t + GRID_P;
        if (tn < NTILES) {
            const float* xb = x + (size_t)(tn >> 5) * DHW + ((tn & 31) << 7);
            uint32_t dstb = sb + ((j & 1) ? SM_X0 : SM_X1);
#pragma unroll
            for (int jj = 0; jj < 4; jj++) {
                int i = tid + jj * 512;
                int d = i >> 5, r4 = (i & 31) << 2;
                CP_ASYNC16(dstb + (d * XLD + r4) * 4,
                           (const char*)(xb + (d << 12) + r4));
            }
        }
        CP_COMMIT();

        // A fragments: 32 rows (2 m16-tiles), full D=64, fp16 hi+lo
        uint32_t Ahi[32], Alo[32];
#pragma unroll
        for (int mt = 0; mt < 2; mt++) {
            int rb = rws * 32 + mt * 16 + grp;
#pragma unroll
            for (int ks = 0; ks < 4; ks++) {
                int kb = ks * 16 + tig * 2;
                int o  = mt * 16 + ks * 4;
                f16_split2(sxc[kb * XLD + rb],           sxc[(kb + 1) * XLD + rb],
                           Ahi[o + 0], Alo[o + 0]);
                f16_split2(sxc[kb * XLD + rb + 8],       sxc[(kb + 1) * XLD + rb + 8],
                           Ahi[o + 1], Alo[o + 1]);
                f16_split2(sxc[(kb + 8) * XLD + rb],     sxc[(kb + 9) * XLD + rb],
                           Ahi[o + 2], Alo[o + 2]);
                f16_split2(sxc[(kb + 8) * XLD + rb + 8], sxc[(kb + 9) * XLD + rb + 8],
                           Ahi[o + 3], Alo[o + 3]);
            }
        }

        float best[4] = {3.4e38f, 3.4e38f, 3.4e38f, 3.4e38f};
        int   idx[4]  = {0, 0, 0, 0};

#pragma unroll 2
        for (int np = 0; np < 8; np++) {
            int ntA = (qtr << 4) + 2 * np;
            float acc[4][4] = {{0.f,0.f,0.f,0.f},{0.f,0.f,0.f,0.f},
                               {0.f,0.f,0.f,0.f},{0.f,0.f,0.f,0.f}};
#pragma unroll
            for (int ks = 0; ks < 4; ks++) {
                uint32_t a0 = sb + SM_FRAG + ((((ntA << 2) + ks) << 5) + lid) * 16;
                uint4 bA, bB;
                asm volatile("ld.shared.v4.b32 {%0,%1,%2,%3}, [%4];"
                    : "=r"(bA.x), "=r"(bA.y), "=r"(bA.z), "=r"(bA.w) : "r"(a0));
                asm volatile("ld.shared.v4.b32 {%0,%1,%2,%3}, [%4];"
                    : "=r"(bB.x), "=r"(bB.y), "=r"(bB.z), "=r"(bB.w) : "r"(a0 + 2048));
                const uint32_t* ah0 = &Ahi[ks * 4];
                const uint32_t* al0 = &Alo[ks * 4];
                const uint32_t* ah1 = &Ahi[16 + ks * 4];
                const uint32_t* al1 = &Alo[16 + ks * 4];
                mma_f16(acc[0], ah0, bA.x, bA.y);     // hi*hi
                mma_f16(acc[1], ah0, bB.x, bB.y);
                mma_f16(acc[2], ah1, bA.x, bA.y);
                mma_f16(acc[3], ah1, bB.x, bB.y);
                mma_f16(acc[0], ah0, bA.z, bA.w);     // hi*lo
                mma_f16(acc[1], ah0, bB.z, bB.w);
                mma_f16(acc[2], ah1, bA.z, bA.w);
                mma_f16(acc[3], ah1, bB.z, bB.w);
                mma_f16(acc[0], al0, bA.x, bA.y);     // lo*hi
                mma_f16(acc[1], al0, bB.x, bB.y);
                mma_f16(acc[2], al1, bA.x, bA.y);
                mma_f16(acc[3], al1, bB.x, bB.y);
            }
            int base0 = ntA * 8 + 2 * tig;
            float2 e0 = *(float2*)(sec + base0);
            float2 e1 = *(float2*)(sec + base0 + 8);
            float s;
            // acc[0]: rows (grp, grp+8) of mt0, codes base0/base0+1
            s = fmaf(acc[0][0], -2.f, e0.x); if (s < best[0]) { best[0] = s; idx[0] = base0; }
            s = fmaf(acc[0][1], -2.f, e0.y); if (s < best[0]) { best[0] = s; idx[0] = base0 + 1; }
            s = fmaf(acc[0][2], -2.f, e0.x); if (s < best[1]) { best[1] = s; idx[1] = base0; }
            s = fmaf(acc[0][3], -2.f, e0.y); if (s < best[1]) { best[1] = s; idx[1] = base0 + 1; }
            s = fmaf(acc[1][0], -2.f, e1.x); if (s < best[0]) { best[0] = s; idx[0] = base0 + 8; }
            s = fmaf(acc[1][1], -2.f, e1.y); if (s < best[0]) { best[0] = s; idx[0] = base0 + 9; }
            s = fmaf(acc[1][2], -2.f, e1.x); if (s < best[1]) { best[1] = s; idx[1] = base0 + 8; }
            s = fmaf(acc[1][3], -2.f, e1.y); if (s < best[1]) { best[1] = s; idx[1] = base0 + 9; }
            s = fmaf(acc[2][0], -2.f, e0.x); if (s < best[2]) { best[2] = s; idx[2] = base0; }
            s = fmaf(acc[2][1], -2.f, e0.y); if (s < best[2]) { best[2] = s; idx[2] = base0 + 1; }
            s = fmaf(acc[2][2], -2.f, e0.x); if (s < best[3]) { best[3] = s; idx[3] = base0; }
            s = fmaf(acc[2][3], -2.f, e0.y); if (s < best[3]) { best[3] = s; idx[3] = base0 + 1; }
            s = fmaf(acc[3][0], -2.f, e1.x); if (s < best[2]) { best[2] = s; idx[2] = base0 + 8; }
            s = fmaf(acc[3][1], -2.f, e1.y); if (s < best[2]) { best[2] = s; idx[2] = base0 + 9; }
            s = fmaf(acc[3][2], -2.f, e1.x); if (s < best[3]) { best[3] = s; idx[3] = base0 + 8; }
            s = fmaf(acc[3][3], -2.f, e1.y); if (s < best[3]) { best[3] = s; idx[3] = base0 + 9; }
        }

        // quad-group argmin reduce (tie -> lowest index)
#pragma unroll
        for (int v = 0; v < 4; v++) {
#pragma unroll
            for (int o = 1; o <= 2; o <<= 1) {
                float ob = __shfl_xor_sync(0xffffffffu, best[v], o);
                int   oi = __shfl_xor_sync(0xffffffffu, idx[v], o);
                if (ob < best[v] || (ob == best[v] && oi < idx[v])) { best[v] = ob; idx[v] = oi; }
            }
        }
        if (tig == 0) {
            int rl = rws * 32 + grp;
            sbest[qtr * 128 + rl]      = best[0];
            sbest[qtr * 128 + rl + 8]  = best[1];
            sbest[qtr * 128 + rl + 16] = best[2];
            sbest[qtr * 128 + rl + 24] = best[3];
            sidxh[qtr * 128 + rl]      = idx[0];
            sidxh[qtr * 128 + rl + 8]  = idx[1];
            sidxh[qtr * 128 + rl + 16] = idx[2];
            sidxh[qtr * 128 + rl + 24] = idx[3];
        }
        __syncthreads();
        // 4-way merge (quarter indices ascend -> strict < keeps lowest on tie)
        if (tid < 128) {
            float bb = sbest[tid]; int ii = sidxh[tid];
#pragma unroll
            for (int qq = 1; qq < 4; qq++) {
                float b2 = sbest[qq * 128 + tid];
                if (b2 < bb) { bb = b2; ii = sidxh[qq * 128 + tid]; }
            }
            sidx[tid] = ii;
            atomicAdd(&d_counts[ii], 1);
        }
        __syncthreads();

        // ---- epilogue: coalesced q via SMEM transpose staging, 2 d-halves ----
        float* qb = q + (size_t)b * DHW + hw0;
#pragma unroll
        for (int pass = 0; pass < 2; pass++) {
            // phase A: gather winning code rows (line-coalesced) -> stage sq[r][37]
#pragma unroll
            for (int it = 0; it < 2; it++) {
                int item = tid + it * 512;          // 0..1023
                int r = item >> 3, c = item & 7;
                int ki = sidx[r];
                float4 ev = __ldg((const float4*)(emb + ki * 64 + pass * 32 + c * 4));
                float* sp = sq + r * 37 + c * 4;
                sp[0] = ev.x; sp[1] = ev.y; sp[2] = ev.z; sp[3] = ev.w;
            }
            __syncthreads();
            // phase B: coalesced float4 stores + fused EMA sums
#pragma unroll
            for (int it = 0; it < 2; it++) {
                int item = tid + it * 512;          // 0..1023
                int dd = item >> 5, g = item & 31;  // dd 0..31, 4-row group g
                int d  = pass * 32 + dd;
                float4 ov;
                ov.x = sq[(4 * g)     * 37 + dd];
                ov.y = sq[(4 * g + 1) * 37 + dd];
                ov.z = sq[(4 * g + 2) * 37 + dd];
                ov.w = sq[(4 * g + 3) * 37 + dd];
                ((float4*)(qb + (d << 12)))[g] = ov;
                int k0 = sidx[4 * g], k1 = sidx[4 * g + 1];
                int k2 = sidx[4 * g + 2], k3 = sidx[4 * g + 3];
                const float* xr = sxc + d * XLD + 4 * g;
                atomicAdd(&d_sums[(d << 9) + k0], xr[0]);
                atomicAdd(&d_sums[(d << 9) + k1], xr[1]);
                atomicAdd(&d_sums[(d << 9) + k2], xr[2]);
                atomicAdd(&d_sums[(d << 9) + k3], xr[3]);
            }
            __syncthreads();
        }

        CP_WAIT0();
        __syncthreads();
    }
}

// ---------------------------------------------------------------------------
// Kernel C: counts EMA -> norm factor (single CTA)
// ---------------------------------------------------------------------------
__device__ __forceinline__ int decode_scalar_int(const int* p) {
    int v = *p;
    if (v >= 0 && v < 1000000) return v;
    return (int)__int_as_float(v);
}

__global__ void norm_kernel(const float* __restrict__ ema_c,
                            const int* __restrict__ counter) {
    __shared__ float wsum[16];
    __shared__ float tot;
    int k = threadIdx.x;

    int   cnt  = decode_scalar_int(counter) + 1;
    float bias = 1.f - (float)pow(0.99, (double)cnt);

    float avg_c = (ema_c[k] * 0.99f + (float)d_counts[k] * 0.01f) / bias;

    float s = avg_c;
#pragma unroll
    for (int o = 16; o > 0; o >>= 1) s += __shfl_xor_sync(0xffffffffu, s, o);
    if ((k & 31) == 0) wsum[k >> 5] = s;
    __syncthreads();
    if (k < 32) {
        float t = (k < 16) ? wsum[k] : 0.f;
#pragma unroll
        for (int o = 8; o > 0; o >>= 1) t += __shfl_xor_sync(0xffffffffu, t, o);
        if (k == 0) tot = t;
    }
    __syncthreads();
    float nn   = tot;
    float norm = (avg_c + EPSf) / (nn + Kk * EPSf) * nn;
    d_scale[k] = 1.f / (bias * norm);
}

// ---------------------------------------------------------------------------
// Kernel D: emit new_weight [K, D]
// ---------------------------------------------------------------------------
__global__ __launch_bounds__(256)
void weight_kernel(const float* __restrict__ ema_e,
                   const float* __restrict__ emb,
                   const int* __restrict__ training,
                   float* __restrict__ w) {
    int j = blockIdx.x * 256 + threadIdx.x;    // over [D, K]
    int d = j >> 9;
    int k = j & 511;

    int tr = decode_scalar_int(training);
    if (tr != 0) {
        float nhe = ema_e[j] * 0.99f + d_sums[j] * 0.01f;
        w[(k << 6) + d] = nhe * d_scale[k];
    } else {
        w[(k << 6) + d] = emb[(k << 6) + d];
    }
}

// ---------------------------------------------------------------------------
extern "C" void kernel_launch(void* const* d_in, const int* in_sizes, int n_in,
                              void* d_out, int out_size) {
    const float* x        = (const float*)d_in[0];
    const float* emb      = (const float*)d_in[1];
    const float* ema_c    = (const float*)d_in[2];
    const float* ema_e    = (const float*)d_in[3];
    const int*   counter  = (const int*)d_in[4];
    const int*   training = (const int*)d_in[5];

    float* out = (float*)d_out;
    float* q   = out;                          // [B, D, H, W]
    float* w   = out + (size_t)Bb * DHW;       // [K, D]

    cudaFuncSetAttribute(assign_kernel, cudaFuncAttributeMaxDynamicSharedMemorySize, SM_TOTAL);

    prep_kernel  <<<64,     512>>>(emb);
    assign_kernel<<<GRID_P, 512, SM_TOTAL>>>(x, emb, q);
    norm_kernel  <<<1,      Kk>>>(ema_c, counter);
    weight_kernel<<<Dd * Kk / 256, 256>>>(ema_e, emb, training, w);
}